// round 14
// baseline (speedup 1.0000x reference)
#include <cuda_runtime.h>
#include <math.h>
#include <stdint.h>

#define THRV 0.6f

// ---------------- scratch (device globals: no runtime allocation) ----------
__device__ float g_H[3][16384 * 304];     // MLP hidden per branch (padded 304)
__device__ float g_E[16384 * 3072];       // [B][3][1024]
__device__ float g_C[16384 * 1024];       // common
__device__ float g_CAT[16384 * 2048];     // [weighted_fp_sum | enhanced_common]
__device__ float g_WT1[3][384 * 1024];    // W1^T padded, tf32-rounded
__device__ float g_WT2[3][1024 * 304];    // W2^T padded, tf32-rounded
__device__ float g_enhT[1024 * 1024];
__device__ float g_fusT[1024 * 2048];

// ---------------- helpers ----------------------------------------------------
struct P3 { const float* p0; const float* p1; const float* p2; };
__device__ __forceinline__ const float* sel(const P3& t, int z) {
    return z == 0 ? t.p0 : (z == 1 ? t.p1 : t.p2);
}
__device__ __forceinline__ uint32_t smem_u32(const void* p) {
    uint32_t a;
    asm("{ .reg .u64 t; cvta.to.shared.u64 t, %1; cvt.u32.u64 %0, t; }" : "=r"(a) : "l"(p));
    return a;
}
__device__ __forceinline__ float rna_tf32(float x) {
    uint32_t u;
    asm("cvt.rna.tf32.f32 %0, %1;" : "=r"(u) : "f"(x));
    return __uint_as_float(u);
}
__device__ __forceinline__ uint32_t rna_bits(uint32_t raw) {
    uint32_t u;
    asm("cvt.rna.tf32.f32 %0, %1;" : "=r"(u) : "f"(__uint_as_float(raw)));
    return u;
}
#define CP_ASYNC16(dst, src) asm volatile("cp.async.cg.shared.global [%0], [%1], 16;" :: "r"(dst), "l"(src))
#define CP_COMMIT()          asm volatile("cp.async.commit_group;" ::: "memory")

__device__ __forceinline__ void ldsm4(uint32_t& r0, uint32_t& r1, uint32_t& r2, uint32_t& r3,
                                      uint32_t addr) {
    asm volatile("ldmatrix.sync.aligned.m8n8.x4.shared.b16 {%0,%1,%2,%3}, [%4];"
                 : "=r"(r0), "=r"(r1), "=r"(r2), "=r"(r3) : "r"(addr));
}
__device__ __forceinline__ void mma_tf32(
    float& c0, float& c1, float& c2, float& c3,
    uint32_t a0, uint32_t a1, uint32_t a2, uint32_t a3,
    uint32_t b0, uint32_t b1)
{
    asm volatile(
        "mma.sync.aligned.m16n8k8.row.col.f32.tf32.tf32.f32 "
        "{%0,%1,%2,%3}, {%4,%5,%6,%7}, {%8,%9}, {%0,%1,%2,%3};"
        : "+f"(c0), "+f"(c1), "+f"(c2), "+f"(c3)
        : "r"(a0), "r"(a1), "r"(a2), "r"(a3), "r"(b0), "r"(b1));
}

static constexpr int LDT = 20;                    // conflict-free smem stride
static constexpr int STAGE_F = 128 * LDT;
static constexpr int GSMEM128 = 4 * 2 * STAGE_F * 4; // 81920 B

// ============================================================================
// Kernel A (layer-1 tail): 256 thr, 8 warps (2m x 4n), warp tile 64 x (NT*8)
// ============================================================================
template <int NT>
__device__ __forceinline__ void load_tile128(
    const float* __restrict__ A, int lda, int rowBase,
    const float* __restrict__ Bt, int ldb, int colBase,
    int k0, float* as, float* bs, int tid)
{
#pragma unroll
    for (int i = 0; i < 2; i++) {
        int idx = i * 256 + tid;
        int r = idx >> 2, c = (idx & 3) << 2;
        CP_ASYNC16(smem_u32(as + r * LDT + c), A + (size_t)(rowBase + r) * lda + k0 + c);
    }
#pragma unroll
    for (int i = 0; i < NT / 2; i++) {
        int idx = i * 256 + tid;
        int r = idx >> 2, c = (idx & 3) << 2;
        CP_ASYNC16(smem_u32(bs + r * LDT + c), Bt + (size_t)(colBase + r) * ldb + k0 + c);
    }
    CP_COMMIT();
}

template <int NT, int EPI, bool RA, bool RS>
__global__ void __launch_bounds__(256, 2) tgemm(
    P3 Ap, int lda,
    const float* __restrict__ Bt0, long btStride, int ldb,
    P3 biasP,
    float* __restrict__ C0, long cStride, int ldc,
    int Ntrue, int Nstore, int K, int colOfs,
    const float* __restrict__ X, int ldx)
{
    extern __shared__ float smem[];
    float* As = smem;
    float* Bs = smem + 4 * STAGE_F;

    const int z = blockIdx.z;
    const float* A = sel(Ap, z);
    const float* Bt = Bt0 + (size_t)z * btStride;
    const float* bias = sel(biasP, z);
    float* C = C0 + (size_t)z * cStride;

    const int tid = threadIdx.x;
    const int wid = tid >> 5, lane = tid & 31;
    const int g = lane >> 2, tig = lane & 3;
    const int warp_m = wid & 1, warp_n = wid >> 1;
    const int rowBase = blockIdx.y * 128;
    const int colBase = colOfs + blockIdx.x * (NT * 32);
    const int S = K >> 4;

    const int arow = (warp_m * 64 + (lane & 15)) * LDT + (lane >> 4) * 4;
    const int brow = (warp_n * (NT * 8) + (lane & 7) + ((lane & 16) ? 8 : 0)) * LDT
                   + ((lane & 8) ? 4 : 0);
    const uint32_t aBase = smem_u32(As) + arow * 4;
    const uint32_t bBase = smem_u32(Bs) + brow * 4;

    float acc[4][NT][4];
#pragma unroll
    for (int mt = 0; mt < 4; mt++)
#pragma unroll
        for (int nt = 0; nt < NT; nt++)
#pragma unroll
            for (int q = 0; q < 4; q++) acc[mt][nt][q] = 0.f;

    load_tile128<NT>(A, lda, rowBase, Bt, ldb, colBase, 0, As, Bs, tid);
    load_tile128<NT>(A, lda, rowBase, Bt, ldb, colBase, 16, As + STAGE_F, Bs + STAGE_F, tid);
    load_tile128<NT>(A, lda, rowBase, Bt, ldb, colBase, 32, As + 2 * STAGE_F, Bs + 2 * STAGE_F, tid);

    for (int s = 0; s < S; s++) {
        const int st = s & 3;
        if (s + 2 < S)      asm volatile("cp.async.wait_group 2;" ::: "memory");
        else if (s + 1 < S) asm volatile("cp.async.wait_group 1;" ::: "memory");
        else                asm volatile("cp.async.wait_group 0;" ::: "memory");
        __syncthreads();
        // single barrier per slice: top-of-slice sync proves slice s-1 done,
        // so stage (s+3)&3 == (s-1)&3 is reusable.

        const uint32_t aSt = aBase + st * (STAGE_F * 4);
        const uint32_t bSt = bBase + st * (STAGE_F * 4);
#pragma unroll
        for (int kk = 0; kk < 16; kk += 8) {
            uint32_t af[4][4];
#pragma unroll
            for (int mt = 0; mt < 4; mt++)
                ldsm4(af[mt][0], af[mt][1], af[mt][2], af[mt][3],
                      aSt + (mt * 16 * LDT + kk) * 4);
            if (RA) {
#pragma unroll
                for (int mt = 0; mt < 4; mt++)
#pragma unroll
                    for (int q = 0; q < 4; q++) af[mt][q] = rna_bits(af[mt][q]);
            }
            uint32_t bf[NT][2];
#pragma unroll
            for (int j = 0; j < NT / 2; j++)
                ldsm4(bf[2 * j][0], bf[2 * j][1], bf[2 * j + 1][0], bf[2 * j + 1][1],
                      bSt + (j * 16 * LDT + kk) * 4);
#pragma unroll
            for (int mt = 0; mt < 4; mt++)
#pragma unroll
                for (int nt = 0; nt < NT; nt++)
                    mma_tf32(acc[mt][nt][0], acc[mt][nt][1], acc[mt][nt][2], acc[mt][nt][3],
                             af[mt][0], af[mt][1], af[mt][2], af[mt][3],
                             bf[nt][0], bf[nt][1]);
        }
        if (s + 3 < S)
            load_tile128<NT>(A, lda, rowBase, Bt, ldb, colBase, (s + 3) * 16,
                             As + ((s + 3) & 3) * STAGE_F, Bs + ((s + 3) & 3) * STAGE_F, tid);
    }

#pragma unroll
    for (int mt = 0; mt < 4; mt++) {
#pragma unroll
        for (int nt = 0; nt < NT; nt++) {
            int col = colBase + warp_n * (NT * 8) + nt * 8 + 2 * tig;
            if (col >= Nstore) continue;
#pragma unroll
            for (int half = 0; half < 2; half++) {
                int row = rowBase + warp_m * 64 + mt * 16 + g + half * 8;
                float v0 = 0.f, v1 = 0.f;
                if (col < Ntrue) {
                    v0 = acc[mt][nt][half * 2 + 0] + bias[col];
                    if (EPI == 1) v0 = fmaxf(v0, 0.f);
                    if (RS) v0 = rna_tf32(v0);
                }
                if (col + 1 < Ntrue) {
                    v1 = acc[mt][nt][half * 2 + 1] + bias[col + 1];
                    if (EPI == 1) v1 = fmaxf(v1, 0.f);
                    if (RS) v1 = rna_tf32(v1);
                }
                *reinterpret_cast<float2*>(&C[(size_t)row * ldc + col]) = make_float2(v0, v1);
            }
        }
    }
}

// ============================================================================
// Kernel B (main GEMMs): 128 thr, 4 warps (2m x 2n), warp tile 64x64.
// EPI 0: bias; 1: relu(bias); 2: X*sigmoid(bias); 3: accumulate into C (no bias)
// ============================================================================
__device__ __forceinline__ void load_tile64(
    const float* __restrict__ A, int lda, int rowBase,
    const float* __restrict__ Bt, int ldb, int colBase,
    int k0, float* as, float* bs, int tid)
{
#pragma unroll
    for (int i = 0; i < 4; i++) {
        int idx = i * 128 + tid;
        int r = idx >> 2, c = (idx & 3) << 2;
        CP_ASYNC16(smem_u32(as + r * LDT + c), A + (size_t)(rowBase + r) * lda + k0 + c);
    }
#pragma unroll
    for (int i = 0; i < 4; i++) {
        int idx = i * 128 + tid;
        int r = idx >> 2, c = (idx & 3) << 2;
        CP_ASYNC16(smem_u32(bs + r * LDT + c), Bt + (size_t)(colBase + r) * ldb + k0 + c);
    }
    CP_COMMIT();
}

template <int EPI, bool RA, bool RS>
__global__ void __launch_bounds__(128, 2) tgemm64(
    P3 Ap, int lda,
    const float* __restrict__ Bt0, long btStride, int ldb,
    P3 biasP,
    float* __restrict__ C0, long cStride, int ldc,
    int K,
    const float* __restrict__ X, int ldx)
{
    extern __shared__ float smem[];
    float* As = smem;
    float* Bs = smem + 4 * STAGE_F;

    const int z = blockIdx.z;
    const float* A = sel(Ap, z);
    const float* Bt = Bt0 + (size_t)z * btStride;
    const float* bias = sel(biasP, z);
    float* C = C0 + (size_t)z * cStride;

    const int tid = threadIdx.x;
    const int wid = tid >> 5, lane = tid & 31;
    const int g = lane >> 2, tig = lane & 3;
    const int warp_m = wid & 1, warp_n = wid >> 1;   // 2 x 2
    const int rowBase = blockIdx.y * 128;
    const int colBase = blockIdx.x * 128;
    const int S = K >> 4;

    const int arow = (warp_m * 64 + (lane & 15)) * LDT + (lane >> 4) * 4;
    const int brow = (warp_n * 64 + (lane & 7) + ((lane & 16) ? 8 : 0)) * LDT
                   + ((lane & 8) ? 4 : 0);
    const uint32_t aBase = smem_u32(As) + arow * 4;
    const uint32_t bBase = smem_u32(Bs) + brow * 4;

    float acc[4][8][4];
#pragma unroll
    for (int mt = 0; mt < 4; mt++)
#pragma unroll
        for (int nt = 0; nt < 8; nt++)
#pragma unroll
            for (int q = 0; q < 4; q++) acc[mt][nt][q] = 0.f;

    load_tile64(A, lda, rowBase, Bt, ldb, colBase, 0, As, Bs, tid);
    load_tile64(A, lda, rowBase, Bt, ldb, colBase, 16, As + STAGE_F, Bs + STAGE_F, tid);
    load_tile64(A, lda, rowBase, Bt, ldb, colBase, 32, As + 2 * STAGE_F, Bs + 2 * STAGE_F, tid);

    for (int s = 0; s < S; s++) {
        const int st = s & 3;
        if (s + 2 < S)      asm volatile("cp.async.wait_group 2;" ::: "memory");
        else if (s + 1 < S) asm volatile("cp.async.wait_group 1;" ::: "memory");
        else                asm volatile("cp.async.wait_group 0;" ::: "memory");
        __syncthreads();
        // single barrier per slice (see kernel A comment)

        const uint32_t aSt = aBase + st * (STAGE_F * 4);
        const uint32_t bSt = bBase + st * (STAGE_F * 4);
#pragma unroll
        for (int kk = 0; kk < 16; kk += 8) {
            uint32_t af[4][4];
#pragma unroll
            for (int mt = 0; mt < 4; mt++)
                ldsm4(af[mt][0], af[mt][1], af[mt][2], af[mt][3],
                      aSt + (mt * 16 * LDT + kk) * 4);
            if (RA) {
#pragma unroll
                for (int mt = 0; mt < 4; mt++)
#pragma unroll
                    for (int q = 0; q < 4; q++) af[mt][q] = rna_bits(af[mt][q]);
            }
            uint32_t bf[8][2];
#pragma unroll
            for (int j = 0; j < 4; j++)
                ldsm4(bf[2 * j][0], bf[2 * j][1], bf[2 * j + 1][0], bf[2 * j + 1][1],
                      bSt + (j * 16 * LDT + kk) * 4);
#pragma unroll
            for (int mt = 0; mt < 4; mt++)
#pragma unroll
                for (int nt = 0; nt < 8; nt++)
                    mma_tf32(acc[mt][nt][0], acc[mt][nt][1], acc[mt][nt][2], acc[mt][nt][3],
                             af[mt][0], af[mt][1], af[mt][2], af[mt][3],
                             bf[nt][0], bf[nt][1]);
        }
        if (s + 3 < S)
            load_tile64(A, lda, rowBase, Bt, ldb, colBase, (s + 3) * 16,
                        As + ((s + 3) & 3) * STAGE_F, Bs + ((s + 3) & 3) * STAGE_F, tid);
    }

#pragma unroll
    for (int mt = 0; mt < 4; mt++) {
#pragma unroll
        for (int nt = 0; nt < 8; nt++) {
            int col = colBase + warp_n * 64 + nt * 8 + 2 * tig;
#pragma unroll
            for (int half = 0; half < 2; half++) {
                int row = rowBase + warp_m * 64 + mt * 16 + g + half * 8;
                float* cp = &C[(size_t)row * ldc + col];
                float v0 = acc[mt][nt][half * 2 + 0];
                float v1 = acc[mt][nt][half * 2 + 1];
                if (EPI == 3) {
                    float2 prev = *reinterpret_cast<const float2*>(cp);
                    v0 += prev.x; v1 += prev.y;
                } else {
                    v0 += bias[col]; v1 += bias[col + 1];
                }
                if (EPI == 1) { v0 = fmaxf(v0, 0.f); v1 = fmaxf(v1, 0.f); }
                if (EPI == 2) {
                    float2 xv = *reinterpret_cast<const float2*>(&X[(size_t)row * ldx + col]);
                    v0 = xv.x / (1.f + expf(-v0));
                    v1 = xv.y / (1.f + expf(-v1));
                }
                if (RS) { v0 = rna_tf32(v0); v1 = rna_tf32(v1); }
                *reinterpret_cast<float2*>(cp) = make_float2(v0, v1);
            }
        }
    }
}

// ---------------- transpose + tf32-round weights (z-batched) -----------------
__global__ void __launch_bounds__(256) transposeW(
    P3 Wp, float* __restrict__ WT0, long wtStride,
    int K, int N, int Kpad, int Npad)
{
    __shared__ float t[32][33];
    const float* W = sel(Wp, blockIdx.z);
    float* WT = WT0 + (size_t)blockIdx.z * wtStride;
    int kb = blockIdx.x * 32, nb = blockIdx.y * 32;
#pragma unroll
    for (int i = 0; i < 4; i++) {
        int kk = kb + threadIdx.y + i * 8, nn = nb + threadIdx.x;
        t[threadIdx.y + i * 8][threadIdx.x] = (kk < K && nn < N) ? W[(size_t)kk * N + nn] : 0.f;
    }
    __syncthreads();
#pragma unroll
    for (int i = 0; i < 4; i++) {
        int nn = nb + threadIdx.y + i * 8, kk = kb + threadIdx.x;
        if (nn < Npad && kk < Kpad)
            WT[(size_t)nn * Kpad + kk] = rna_tf32(t[threadIdx.x][threadIdx.y + i * 8]);
    }
}

// ---------------- per-row fusion (register-resident, float4) -----------------
__global__ __launch_bounds__(256) void rowfuse(
    const float* __restrict__ E, const float* __restrict__ wgW,
    const float* __restrict__ wgb,
    float* __restrict__ common, float* __restrict__ cat)
{
    __shared__ float sred[8][9];
    __shared__ float sc[10];

    const int b = blockIdx.x;
    const int tid = threadIdx.x;
    const float* Erow = E + (size_t)b * 3072;

    const float4 e0 = *reinterpret_cast<const float4*>(Erow + tid * 4);
    const float4 e1 = *reinterpret_cast<const float4*>(Erow + 1024 + tid * 4);
    const float4 e2 = *reinterpret_cast<const float4*>(Erow + 2048 + tid * 4);

    float r[9];
    r[0] = e0.x * e0.x + e0.y * e0.y + e0.z * e0.z + e0.w * e0.w;
    r[1] = e1.x * e1.x + e1.y * e1.y + e1.z * e1.z + e1.w * e1.w;
    r[2] = e2.x * e2.x + e2.y * e2.y + e2.z * e2.z + e2.w * e2.w;
    r[3] = e0.x * e1.x + e0.y * e1.y + e0.z * e1.z + e0.w * e1.w;
    r[4] = e0.x * e2.x + e0.y * e2.y + e0.z * e2.z + e0.w * e2.w;
    r[5] = e1.x * e2.x + e1.y * e2.y + e1.z * e2.z + e1.w * e2.w;
    r[6] = r[7] = r[8] = 0.f;
    {
        const float ev[3][4] = {{e0.x, e0.y, e0.z, e0.w},
                                {e1.x, e1.y, e1.z, e1.w},
                                {e2.x, e2.y, e2.z, e2.w}};
#pragma unroll
        for (int br = 0; br < 3; br++) {
            const float* wp = wgW + (size_t)(br * 1024 + tid * 4) * 3;
#pragma unroll
            for (int i = 0; i < 4; i++) {
                float v = ev[br][i];
                r[6] += v * wp[3 * i + 0];
                r[7] += v * wp[3 * i + 1];
                r[8] += v * wp[3 * i + 2];
            }
        }
    }
#pragma unroll
    for (int q = 0; q < 9; q++)
#pragma unroll
        for (int o = 16; o > 0; o >>= 1) r[q] += __shfl_down_sync(0xffffffffu, r[q], o);

    int warp = tid >> 5, lane = tid & 31;
    if (lane == 0)
#pragma unroll
        for (int q = 0; q < 9; q++) sred[warp][q] = r[q];
    __syncthreads();

    if (tid == 0) {
        float s[9];
#pragma unroll
        for (int q = 0; q < 9; q++) {
            float a = 0.f;
            for (int w2 = 0; w2 < 8; w2++) a += sred[w2][q];
            s[q] = a;
        }
        float inv0 = 1.f / fmaxf(sqrtf(s[0]), 1e-12f);
        float inv1 = 1.f / fmaxf(sqrtf(s[1]), 1e-12f);
        float inv2 = 1.f / fmaxf(sqrtf(s[2]), 1e-12f);
        float sim0 = s[3] * inv0 * inv1;
        float sim1 = s[4] * inv0 * inv2;
        float sim2 = s[5] * inv1 * inv2;
        bool k0 = sim0 > THRV, k1 = sim1 > THRV, k2 = sim2 > THRV;
        float x0 = k0 ? sim0 : -1e9f;
        float x1 = k1 ? sim1 : -1e9f;
        float x2 = k2 ? sim2 : -1e9f;
        float mx = fmaxf(x0, fmaxf(x1, x2));
        float ex0 = expf(x0 - mx), ex1 = expf(x1 - mx), ex2 = expf(x2 - mx);
        float es = ex0 + ex1 + ex2;
        float l0 = s[6] + wgb[0], l1 = s[7] + wgb[1], l2 = s[8] + wgb[2];
        float lm = fmaxf(l0, fmaxf(l1, l2));
        float g0 = expf(l0 - lm), g1 = expf(l1 - lm), g2 = expf(l2 - lm);
        float gs = g0 + g1 + g2;
        sc[0] = inv0; sc[1] = inv1; sc[2] = inv2;
        sc[3] = ex0 / es; sc[4] = ex1 / es; sc[5] = ex2 / es;
        sc[6] = g0 / gs; sc[7] = g1 / gs; sc[8] = g2 / gs;
        sc[9] = (k0 || k1 || k2) ? 1.f : 0.f;
    }
    __syncthreads();

    const float inv0 = sc[0], inv1 = sc[1], inv2 = sc[2];
    const float w0 = sc[3], w1 = sc[4], w2 = sc[5];
    const float f0 = sc[6], f1 = sc[7], f2 = sc[8];
    const bool any = sc[9] > 0.5f;

    float4 cm, ct;
    {
        const float a0[4] = {e0.x, e0.y, e0.z, e0.w};
        const float a1[4] = {e1.x, e1.y, e1.z, e1.w};
        const float a2[4] = {e2.x, e2.y, e2.z, e2.w};
        float cmv[4], ctv[4];
#pragma unroll
        for (int i = 0; i < 4; i++) {
            float v0 = a0[i], v1 = a1[i], v2 = a2[i];
            float n0 = v0 * inv0, n1 = v1 * inv1, n2 = v2 * inv2;
            float wsum = 0.f;
            if (n0 * n1 > THRV) wsum += w0 * 0.5f * (v0 + v1);
            if (n0 * n2 > THRV) wsum += w1 * 0.5f * (v0 + v2);
            if (n1 * n2 > THRV) wsum += w2 * 0.5f * (v1 + v2);
            float mean = (v0 + v1 + v2) * (1.f / 3.f);
            cmv[i] = rna_tf32(any ? wsum : mean);
            ctv[i] = rna_tf32(f0 * v0 + f1 * v1 + f2 * v2);
        }
        cm = make_float4(cmv[0], cmv[1], cmv[2], cmv[3]);
        ct = make_float4(ctv[0], ctv[1], ctv[2], ctv[3]);
    }
    *reinterpret_cast<float4*>(common + (size_t)b * 1024 + tid * 4) = cm;
    *reinterpret_cast<float4*>(cat + (size_t)b * 2048 + tid * 4) = ct;
}

// ---------------------------------------------------------------------------
extern "C" void kernel_launch(void* const* d_in, const int* in_sizes, int n_in,
                              void* d_out, int out_size)
{
    const float* xin[3] = {(const float*)d_in[0], (const float*)d_in[1], (const float*)d_in[2]};
    const float* w1[3]  = {(const float*)d_in[3], (const float*)d_in[7], (const float*)d_in[11]};
    const float* b1[3]  = {(const float*)d_in[4], (const float*)d_in[8], (const float*)d_in[12]};
    const float* w2[3]  = {(const float*)d_in[5], (const float*)d_in[9], (const float*)d_in[13]};
    const float* b2[3]  = {(const float*)d_in[6], (const float*)d_in[10], (const float*)d_in[14]};
    const float* wgW = (const float*)d_in[15]; const float* wgb = (const float*)d_in[16];
    const float* enhW = (const float*)d_in[17]; const float* enhb = (const float*)d_in[18];
    const float* fusW = (const float*)d_in[19]; const float* fusb = (const float*)d_in[20];
    float* out = (float*)d_out;

    float *H, *E, *C, *CAT, *WT1, *WT2, *ENT, *FUT;
    cudaGetSymbolAddress((void**)&H, g_H);
    cudaGetSymbolAddress((void**)&E, g_E);
    cudaGetSymbolAddress((void**)&C, g_C);
    cudaGetSymbolAddress((void**)&CAT, g_CAT);
    cudaGetSymbolAddress((void**)&WT1, g_WT1);
    cudaGetSymbolAddress((void**)&WT2, g_WT2);
    cudaGetSymbolAddress((void**)&ENT, g_enhT);
    cudaGetSymbolAddress((void**)&FUT, g_fusT);

    static cudaStream_t s2 = nullptr;
    static cudaEvent_t ev1 = nullptr, ev2 = nullptr, ev3 = nullptr, ev4 = nullptr;
    static bool init_done = false;
    if (!init_done) {
        cudaFuncSetAttribute((const void*)tgemm<2, 1, true, true>,  cudaFuncAttributeMaxDynamicSharedMemorySize, GSMEM128);
        cudaFuncSetAttribute((const void*)tgemm64<1, true, true>,   cudaFuncAttributeMaxDynamicSharedMemorySize, GSMEM128);
        cudaFuncSetAttribute((const void*)tgemm64<0, false, false>, cudaFuncAttributeMaxDynamicSharedMemorySize, GSMEM128);
        cudaFuncSetAttribute((const void*)tgemm64<2, false, true>,  cudaFuncAttributeMaxDynamicSharedMemorySize, GSMEM128);
        cudaFuncSetAttribute((const void*)tgemm64<3, false, false>, cudaFuncAttributeMaxDynamicSharedMemorySize, GSMEM128);
        cudaStreamCreateWithFlags(&s2, cudaStreamNonBlocking);
        cudaEventCreateWithFlags(&ev1, cudaEventDisableTiming);
        cudaEventCreateWithFlags(&ev2, cudaEventDisableTiming);
        cudaEventCreateWithFlags(&ev3, cudaEventDisableTiming);
        cudaEventCreateWithFlags(&ev4, cudaEventDisableTiming);
        init_done = true;
    }

    dim3 tb(32, 8);
    const int Mt = 16384 / 128;  // 128 M-tiles
    const long HSTR = 16384L * 304;

    // weight transposes (tf32-rounded) on the main stream (WT1 gates layer-1)
    P3 w1p = {w1[0], w1[1], w1[2]};
    P3 w2p = {w2[0], w2[1], w2[2]};
    transposeW<<<dim3(32, 12, 3), tb>>>(w1p, WT1, 384L * 1024, 1024, 300, 1024, 384);
    transposeW<<<dim3(10, 32, 3), tb>>>(w2p, WT2, 1024L * 304, 300, 1024, 304, 1024);

    // fork side stream: L1 tail + enh/fus transposes overlap L1 main
    cudaEventRecord(ev1, 0);
    cudaStreamWaitEvent(s2, ev1, 0);

    P3 aL1 = {xin[0], xin[1], xin[2]};
    P3 bL1 = {b1[0], b1[1], b1[2]};
    tgemm<2, 1, true, true><<<dim3(1, Mt, 3), 256, GSMEM128, s2>>>(
        aL1, 1024, WT1, 384L * 1024, 1024, bL1,
        H, HSTR, 304, 300, 304, 1024, 256, nullptr, 0);
    P3 enhp = {enhW, enhW, enhW};
    P3 fusp = {fusW, fusW, fusW};
    transposeW<<<dim3(32, 32, 1), tb, 0, s2>>>(enhp, ENT, 0, 1024, 1024, 1024, 1024);
    transposeW<<<dim3(64, 32, 1), tb, 0, s2>>>(fusp, FUT, 0, 2048, 1024, 2048, 1024);
    cudaEventRecord(ev2, s2);

    // main stream: L1 main (cols 0-255)
    tgemm64<1, true, true><<<dim3(2, Mt, 3), 128, GSMEM128>>>(
        aL1, 1024, WT1, 384L * 1024, 1024, bL1,
        H, HSTR, 304, 1024, nullptr, 0);

    // join before L2 (needs full H; also covers ENT/FUT)
    cudaStreamWaitEvent(0, ev2, 0);

    // Layer 2 batched: E[:, z, :] = H_z @ W2_z + b2_z (K=304)
    P3 aL2 = {H, H + HSTR, H + 2 * HSTR};
    P3 bL2 = {b2[0], b2[1], b2[2]};
    tgemm64<0, false, false><<<dim3(8, Mt, 3), 128, GSMEM128>>>(
        aL2, 304, WT2, 1024L * 304, 304, bL2,
        E, 1024, 3072, 304, nullptr, 0);

    rowfuse<<<16384, 256>>>(E, wgW, wgb, C, CAT);

    // fork after rowfuse: fus part-1 (CAT[:, :1024] @ FUT[:, :1024] + bias)
    // on s2, overlapped with enh on the main stream.
    cudaEventRecord(ev3, 0);
    cudaStreamWaitEvent(s2, ev3, 0);
    P3 aFU1 = {CAT, CAT, CAT};
    P3 bFU = {fusb, fusb, fusb};
    tgemm64<0, false, false><<<dim3(8, Mt, 1), 128, GSMEM128, s2>>>(
        aFU1, 2048, FUT, 0, 2048, bFU,
        out, 0, 1024, 1024, nullptr, 0);
    cudaEventRecord(ev4, s2);

    // main stream: CAT[:,1024:] = C * sigmoid(C @ enhW + enhb)
    P3 aEN = {C, C, C};
    P3 bEN = {enhb, enhb, enhb};
    tgemm64<2, false, true><<<dim3(8, Mt, 1), 128, GSMEM128>>>(
        aEN, 1024, ENT, 0, 1024, bEN,
        CAT + 1024, 0, 2048, 1024, C, 1024);

    // join, then fus part-2 accumulates CAT[:,1024:] @ FUT[:,1024:]
    cudaStreamWaitEvent(0, ev4, 0);
    P3 aFU2 = {CAT + 1024, CAT + 1024, CAT + 1024};
    tgemm64<3, false, false><<<dim3(8, Mt, 1), 128, GSMEM128>>>(
        aFU2, 2048, FUT + 1024, 0, 2048, bFU,
        out, 0, 1024, 1024, nullptr, 0);
}

// round 15
// speedup vs baseline: 1.1238x; 1.1238x over previous
#include <cuda_runtime.h>
#include <math.h>
#include <stdint.h>

#define THRV 0.6f

// ---------------- scratch (device globals: no runtime allocation) ----------
__device__ float g_H[3][16384 * 304];     // MLP hidden per branch (padded 304)
__device__ float g_E[16384 * 3072];       // [B][3][1024]
__device__ float g_C[16384 * 1024];       // common
__device__ float g_CAT[16384 * 2048];     // [weighted_fp_sum | enhanced_common]
__device__ float g_WT1[3][384 * 1024];    // W1^T padded, tf32-rounded
__device__ float g_WT2[3][1024 * 304];    // W2^T padded, tf32-rounded
__device__ float g_enhT[1024 * 1024];
__device__ float g_fusT[1024 * 2048];

// ---------------- helpers ----------------------------------------------------
struct P3 { const float* p0; const float* p1; const float* p2; };
__device__ __forceinline__ const float* sel(const P3& t, int z) {
    return z == 0 ? t.p0 : (z == 1 ? t.p1 : t.p2);
}
__device__ __forceinline__ uint32_t smem_u32(const void* p) {
    uint32_t a;
    asm("{ .reg .u64 t; cvta.to.shared.u64 t, %1; cvt.u32.u64 %0, t; }" : "=r"(a) : "l"(p));
    return a;
}
__device__ __forceinline__ float rna_tf32(float x) {
    uint32_t u;
    asm("cvt.rna.tf32.f32 %0, %1;" : "=r"(u) : "f"(x));
    return __uint_as_float(u);
}
__device__ __forceinline__ uint32_t rna_bits(uint32_t raw) {
    uint32_t u;
    asm("cvt.rna.tf32.f32 %0, %1;" : "=r"(u) : "f"(__uint_as_float(raw)));
    return u;
}
#define CP_ASYNC16(dst, src) asm volatile("cp.async.cg.shared.global [%0], [%1], 16;" :: "r"(dst), "l"(src))
#define CP_COMMIT()          asm volatile("cp.async.commit_group;" ::: "memory")

__device__ __forceinline__ void ldsm4(uint32_t& r0, uint32_t& r1, uint32_t& r2, uint32_t& r3,
                                      uint32_t addr) {
    asm volatile("ldmatrix.sync.aligned.m8n8.x4.shared.b16 {%0,%1,%2,%3}, [%4];"
                 : "=r"(r0), "=r"(r1), "=r"(r2), "=r"(r3) : "r"(addr));
}
__device__ __forceinline__ void mma_tf32(
    float& c0, float& c1, float& c2, float& c3,
    uint32_t a0, uint32_t a1, uint32_t a2, uint32_t a3,
    uint32_t b0, uint32_t b1)
{
    asm volatile(
        "mma.sync.aligned.m16n8k8.row.col.f32.tf32.tf32.f32 "
        "{%0,%1,%2,%3}, {%4,%5,%6,%7}, {%8,%9}, {%0,%1,%2,%3};"
        : "+f"(c0), "+f"(c1), "+f"(c2), "+f"(c3)
        : "r"(a0), "r"(a1), "r"(a2), "r"(a3), "r"(b0), "r"(b1));
}

static constexpr int LDT = 20;                    // conflict-free smem stride
static constexpr int STAGE_F = 128 * LDT;
static constexpr int GSMEM128 = 4 * 2 * STAGE_F * 4; // 81920 B

// ============================================================================
// Kernel A (layer-1 tail): 256 thr, 8 warps (2m x 4n), warp tile 64 x (NT*8)
// ============================================================================
template <int NT>
__device__ __forceinline__ void load_tile128(
    const float* __restrict__ A, int lda, int rowBase,
    const float* __restrict__ Bt, int ldb, int colBase,
    int k0, float* as, float* bs, int tid)
{
#pragma unroll
    for (int i = 0; i < 2; i++) {
        int idx = i * 256 + tid;
        int r = idx >> 2, c = (idx & 3) << 2;
        CP_ASYNC16(smem_u32(as + r * LDT + c), A + (size_t)(rowBase + r) * lda + k0 + c);
    }
#pragma unroll
    for (int i = 0; i < NT / 2; i++) {
        int idx = i * 256 + tid;
        int r = idx >> 2, c = (idx & 3) << 2;
        CP_ASYNC16(smem_u32(bs + r * LDT + c), Bt + (size_t)(colBase + r) * ldb + k0 + c);
    }
    CP_COMMIT();
}

template <int NT, int EPI, bool RA, bool RS>
__global__ void __launch_bounds__(256, 2) tgemm(
    P3 Ap, int lda,
    const float* __restrict__ Bt0, long btStride, int ldb,
    P3 biasP,
    float* __restrict__ C0, long cStride, int ldc,
    int Ntrue, int Nstore, int K, int colOfs,
    const float* __restrict__ X, int ldx)
{
    extern __shared__ float smem[];
    float* As = smem;
    float* Bs = smem + 4 * STAGE_F;

    const int z = blockIdx.z;
    const float* A = sel(Ap, z);
    const float* Bt = Bt0 + (size_t)z * btStride;
    const float* bias = sel(biasP, z);
    float* C = C0 + (size_t)z * cStride;

    const int tid = threadIdx.x;
    const int wid = tid >> 5, lane = tid & 31;
    const int g = lane >> 2, tig = lane & 3;
    const int warp_m = wid & 1, warp_n = wid >> 1;
    const int rowBase = blockIdx.y * 128;
    const int colBase = colOfs + blockIdx.x * (NT * 32);
    const int S = K >> 4;

    const int arow = (warp_m * 64 + (lane & 15)) * LDT + (lane >> 4) * 4;
    const int brow = (warp_n * (NT * 8) + (lane & 7) + ((lane & 16) ? 8 : 0)) * LDT
                   + ((lane & 8) ? 4 : 0);
    const uint32_t aBase = smem_u32(As) + arow * 4;
    const uint32_t bBase = smem_u32(Bs) + brow * 4;

    float acc[4][NT][4];
#pragma unroll
    for (int mt = 0; mt < 4; mt++)
#pragma unroll
        for (int nt = 0; nt < NT; nt++)
#pragma unroll
            for (int q = 0; q < 4; q++) acc[mt][nt][q] = 0.f;

    load_tile128<NT>(A, lda, rowBase, Bt, ldb, colBase, 0, As, Bs, tid);
    load_tile128<NT>(A, lda, rowBase, Bt, ldb, colBase, 16, As + STAGE_F, Bs + STAGE_F, tid);
    load_tile128<NT>(A, lda, rowBase, Bt, ldb, colBase, 32, As + 2 * STAGE_F, Bs + 2 * STAGE_F, tid);

    for (int s = 0; s < S; s++) {
        const int st = s & 3;
        if (s + 2 < S)      asm volatile("cp.async.wait_group 2;" ::: "memory");
        else if (s + 1 < S) asm volatile("cp.async.wait_group 1;" ::: "memory");
        else                asm volatile("cp.async.wait_group 0;" ::: "memory");
        __syncthreads();
        // single barrier per slice: top-of-slice sync proves slice s-1 done,
        // so stage (s+3)&3 == (s-1)&3 is reusable.

        const uint32_t aSt = aBase + st * (STAGE_F * 4);
        const uint32_t bSt = bBase + st * (STAGE_F * 4);
#pragma unroll
        for (int kk = 0; kk < 16; kk += 8) {
            uint32_t af[4][4];
#pragma unroll
            for (int mt = 0; mt < 4; mt++)
                ldsm4(af[mt][0], af[mt][1], af[mt][2], af[mt][3],
                      aSt + (mt * 16 * LDT + kk) * 4);
            if (RA) {
#pragma unroll
                for (int mt = 0; mt < 4; mt++)
#pragma unroll
                    for (int q = 0; q < 4; q++) af[mt][q] = rna_bits(af[mt][q]);
            }
            uint32_t bf[NT][2];
#pragma unroll
            for (int j = 0; j < NT / 2; j++)
                ldsm4(bf[2 * j][0], bf[2 * j][1], bf[2 * j + 1][0], bf[2 * j + 1][1],
                      bSt + (j * 16 * LDT + kk) * 4);
#pragma unroll
            for (int mt = 0; mt < 4; mt++)
#pragma unroll
                for (int nt = 0; nt < NT; nt++)
                    mma_tf32(acc[mt][nt][0], acc[mt][nt][1], acc[mt][nt][2], acc[mt][nt][3],
                             af[mt][0], af[mt][1], af[mt][2], af[mt][3],
                             bf[nt][0], bf[nt][1]);
        }
        if (s + 3 < S)
            load_tile128<NT>(A, lda, rowBase, Bt, ldb, colBase, (s + 3) * 16,
                             As + ((s + 3) & 3) * STAGE_F, Bs + ((s + 3) & 3) * STAGE_F, tid);
    }

#pragma unroll
    for (int mt = 0; mt < 4; mt++) {
#pragma unroll
        for (int nt = 0; nt < NT; nt++) {
            int col = colBase + warp_n * (NT * 8) + nt * 8 + 2 * tig;
            if (col >= Nstore) continue;
#pragma unroll
            for (int half = 0; half < 2; half++) {
                int row = rowBase + warp_m * 64 + mt * 16 + g + half * 8;
                float v0 = 0.f, v1 = 0.f;
                if (col < Ntrue) {
                    v0 = acc[mt][nt][half * 2 + 0] + bias[col];
                    if (EPI == 1) v0 = fmaxf(v0, 0.f);
                    if (RS) v0 = rna_tf32(v0);
                }
                if (col + 1 < Ntrue) {
                    v1 = acc[mt][nt][half * 2 + 1] + bias[col + 1];
                    if (EPI == 1) v1 = fmaxf(v1, 0.f);
                    if (RS) v1 = rna_tf32(v1);
                }
                *reinterpret_cast<float2*>(&C[(size_t)row * ldc + col]) = make_float2(v0, v1);
            }
        }
    }
}

// ============================================================================
// Kernel B (main GEMMs): 128 thr, 4 warps (2m x 2n), warp tile 64x64.
// rowOfs: M-tile offset for half-batch pipelining.
// EPI 0: bias; 1: relu(bias); 2: X*sigmoid(bias)
// ============================================================================
__device__ __forceinline__ void load_tile64(
    const float* __restrict__ A, int lda, int rowBase,
    const float* __restrict__ Bt, int ldb, int colBase,
    int k0, float* as, float* bs, int tid)
{
#pragma unroll
    for (int i = 0; i < 4; i++) {
        int idx = i * 128 + tid;
        int r = idx >> 2, c = (idx & 3) << 2;
        CP_ASYNC16(smem_u32(as + r * LDT + c), A + (size_t)(rowBase + r) * lda + k0 + c);
    }
#pragma unroll
    for (int i = 0; i < 4; i++) {
        int idx = i * 128 + tid;
        int r = idx >> 2, c = (idx & 3) << 2;
        CP_ASYNC16(smem_u32(bs + r * LDT + c), Bt + (size_t)(colBase + r) * ldb + k0 + c);
    }
    CP_COMMIT();
}

template <int EPI, bool RA, bool RS>
__global__ void __launch_bounds__(128, 2) tgemm64(
    P3 Ap, int lda,
    const float* __restrict__ Bt0, long btStride, int ldb,
    P3 biasP,
    float* __restrict__ C0, long cStride, int ldc,
    int K, int rowOfs,
    const float* __restrict__ X, int ldx)
{
    extern __shared__ float smem[];
    float* As = smem;
    float* Bs = smem + 4 * STAGE_F;

    const int z = blockIdx.z;
    const float* A = sel(Ap, z);
    const float* Bt = Bt0 + (size_t)z * btStride;
    const float* bias = sel(biasP, z);
    float* C = C0 + (size_t)z * cStride;

    const int tid = threadIdx.x;
    const int wid = tid >> 5, lane = tid & 31;
    const int g = lane >> 2, tig = lane & 3;
    const int warp_m = wid & 1, warp_n = wid >> 1;   // 2 x 2
    const int rowBase = (blockIdx.y + rowOfs) * 128;
    const int colBase = blockIdx.x * 128;
    const int S = K >> 4;

    const int arow = (warp_m * 64 + (lane & 15)) * LDT + (lane >> 4) * 4;
    const int brow = (warp_n * 64 + (lane & 7) + ((lane & 16) ? 8 : 0)) * LDT
                   + ((lane & 8) ? 4 : 0);
    const uint32_t aBase = smem_u32(As) + arow * 4;
    const uint32_t bBase = smem_u32(Bs) + brow * 4;

    float acc[4][8][4];
#pragma unroll
    for (int mt = 0; mt < 4; mt++)
#pragma unroll
        for (int nt = 0; nt < 8; nt++)
#pragma unroll
            for (int q = 0; q < 4; q++) acc[mt][nt][q] = 0.f;

    load_tile64(A, lda, rowBase, Bt, ldb, colBase, 0, As, Bs, tid);
    load_tile64(A, lda, rowBase, Bt, ldb, colBase, 16, As + STAGE_F, Bs + STAGE_F, tid);
    load_tile64(A, lda, rowBase, Bt, ldb, colBase, 32, As + 2 * STAGE_F, Bs + 2 * STAGE_F, tid);

    for (int s = 0; s < S; s++) {
        const int st = s & 3;
        if (s + 2 < S)      asm volatile("cp.async.wait_group 2;" ::: "memory");
        else if (s + 1 < S) asm volatile("cp.async.wait_group 1;" ::: "memory");
        else                asm volatile("cp.async.wait_group 0;" ::: "memory");
        __syncthreads();
        // single barrier per slice (see kernel A comment)

        const uint32_t aSt = aBase + st * (STAGE_F * 4);
        const uint32_t bSt = bBase + st * (STAGE_F * 4);
#pragma unroll
        for (int kk = 0; kk < 16; kk += 8) {
            uint32_t af[4][4];
#pragma unroll
            for (int mt = 0; mt < 4; mt++)
                ldsm4(af[mt][0], af[mt][1], af[mt][2], af[mt][3],
                      aSt + (mt * 16 * LDT + kk) * 4);
            if (RA) {
#pragma unroll
                for (int mt = 0; mt < 4; mt++)
#pragma unroll
                    for (int q = 0; q < 4; q++) af[mt][q] = rna_bits(af[mt][q]);
            }
            uint32_t bf[8][2];
#pragma unroll
            for (int j = 0; j < 4; j++)
                ldsm4(bf[2 * j][0], bf[2 * j][1], bf[2 * j + 1][0], bf[2 * j + 1][1],
                      bSt + (j * 16 * LDT + kk) * 4);
#pragma unroll
            for (int mt = 0; mt < 4; mt++)
#pragma unroll
                for (int nt = 0; nt < 8; nt++)
                    mma_tf32(acc[mt][nt][0], acc[mt][nt][1], acc[mt][nt][2], acc[mt][nt][3],
                             af[mt][0], af[mt][1], af[mt][2], af[mt][3],
                             bf[nt][0], bf[nt][1]);
        }
        if (s + 3 < S)
            load_tile64(A, lda, rowBase, Bt, ldb, colBase, (s + 3) * 16,
                        As + ((s + 3) & 3) * STAGE_F, Bs + ((s + 3) & 3) * STAGE_F, tid);
    }

#pragma unroll
    for (int mt = 0; mt < 4; mt++) {
#pragma unroll
        for (int nt = 0; nt < 8; nt++) {
            int col = colBase + warp_n * 64 + nt * 8 + 2 * tig;
#pragma unroll
            for (int half = 0; half < 2; half++) {
                int row = rowBase + warp_m * 64 + mt * 16 + g + half * 8;
                float v0 = acc[mt][nt][half * 2 + 0] + bias[col];
                float v1 = acc[mt][nt][half * 2 + 1] + bias[col + 1];
                if (EPI == 1) { v0 = fmaxf(v0, 0.f); v1 = fmaxf(v1, 0.f); }
                if (EPI == 2) {
                    float2 xv = *reinterpret_cast<const float2*>(&X[(size_t)row * ldx + col]);
                    v0 = xv.x / (1.f + expf(-v0));
                    v1 = xv.y / (1.f + expf(-v1));
                }
                if (RS) { v0 = rna_tf32(v0); v1 = rna_tf32(v1); }
                *reinterpret_cast<float2*>(&C[(size_t)row * ldc + col]) = make_float2(v0, v1);
            }
        }
    }
}

// ---------------- transpose + tf32-round weights (z-batched) -----------------
__global__ void __launch_bounds__(256) transposeW(
    P3 Wp, float* __restrict__ WT0, long wtStride,
    int K, int N, int Kpad, int Npad)
{
    __shared__ float t[32][33];
    const float* W = sel(Wp, blockIdx.z);
    float* WT = WT0 + (size_t)blockIdx.z * wtStride;
    int kb = blockIdx.x * 32, nb = blockIdx.y * 32;
#pragma unroll
    for (int i = 0; i < 4; i++) {
        int kk = kb + threadIdx.y + i * 8, nn = nb + threadIdx.x;
        t[threadIdx.y + i * 8][threadIdx.x] = (kk < K && nn < N) ? W[(size_t)kk * N + nn] : 0.f;
    }
    __syncthreads();
#pragma unroll
    for (int i = 0; i < 4; i++) {
        int nn = nb + threadIdx.y + i * 8, kk = kb + threadIdx.x;
        if (nn < Npad && kk < Kpad)
            WT[(size_t)nn * Kpad + kk] = rna_tf32(t[threadIdx.x][threadIdx.y + i * 8]);
    }
}

// ---------------- per-row fusion (register-resident, float4) -----------------
__global__ __launch_bounds__(256) void rowfuse(
    const float* __restrict__ E, const float* __restrict__ wgW,
    const float* __restrict__ wgb,
    float* __restrict__ common, float* __restrict__ cat, int bOfs)
{
    __shared__ float sred[8][9];
    __shared__ float sc[10];

    const int b = blockIdx.x + bOfs;
    const int tid = threadIdx.x;
    const float* Erow = E + (size_t)b * 3072;

    const float4 e0 = *reinterpret_cast<const float4*>(Erow + tid * 4);
    const float4 e1 = *reinterpret_cast<const float4*>(Erow + 1024 + tid * 4);
    const float4 e2 = *reinterpret_cast<const float4*>(Erow + 2048 + tid * 4);

    float r[9];
    r[0] = e0.x * e0.x + e0.y * e0.y + e0.z * e0.z + e0.w * e0.w;
    r[1] = e1.x * e1.x + e1.y * e1.y + e1.z * e1.z + e1.w * e1.w;
    r[2] = e2.x * e2.x + e2.y * e2.y + e2.z * e2.z + e2.w * e2.w;
    r[3] = e0.x * e1.x + e0.y * e1.y + e0.z * e1.z + e0.w * e1.w;
    r[4] = e0.x * e2.x + e0.y * e2.y + e0.z * e2.z + e0.w * e2.w;
    r[5] = e1.x * e2.x + e1.y * e2.y + e1.z * e2.z + e1.w * e2.w;
    r[6] = r[7] = r[8] = 0.f;
    {
        const float ev[3][4] = {{e0.x, e0.y, e0.z, e0.w},
                                {e1.x, e1.y, e1.z, e1.w},
                                {e2.x, e2.y, e2.z, e2.w}};
#pragma unroll
        for (int br = 0; br < 3; br++) {
            const float* wp = wgW + (size_t)(br * 1024 + tid * 4) * 3;
#pragma unroll
            for (int i = 0; i < 4; i++) {
                float v = ev[br][i];
                r[6] += v * wp[3 * i + 0];
                r[7] += v * wp[3 * i + 1];
                r[8] += v * wp[3 * i + 2];
            }
        }
    }
#pragma unroll
    for (int q = 0; q < 9; q++)
#pragma unroll
        for (int o = 16; o > 0; o >>= 1) r[q] += __shfl_down_sync(0xffffffffu, r[q], o);

    int warp = tid >> 5, lane = tid & 31;
    if (lane == 0)
#pragma unroll
        for (int q = 0; q < 9; q++) sred[warp][q] = r[q];
    __syncthreads();

    if (tid == 0) {
        float s[9];
#pragma unroll
        for (int q = 0; q < 9; q++) {
            float a = 0.f;
            for (int w2 = 0; w2 < 8; w2++) a += sred[w2][q];
            s[q] = a;
        }
        float inv0 = 1.f / fmaxf(sqrtf(s[0]), 1e-12f);
        float inv1 = 1.f / fmaxf(sqrtf(s[1]), 1e-12f);
        float inv2 = 1.f / fmaxf(sqrtf(s[2]), 1e-12f);
        float sim0 = s[3] * inv0 * inv1;
        float sim1 = s[4] * inv0 * inv2;
        float sim2 = s[5] * inv1 * inv2;
        bool k0 = sim0 > THRV, k1 = sim1 > THRV, k2 = sim2 > THRV;
        float x0 = k0 ? sim0 : -1e9f;
        float x1 = k1 ? sim1 : -1e9f;
        float x2 = k2 ? sim2 : -1e9f;
        float mx = fmaxf(x0, fmaxf(x1, x2));
        float ex0 = expf(x0 - mx), ex1 = expf(x1 - mx), ex2 = expf(x2 - mx);
        float es = ex0 + ex1 + ex2;
        float l0 = s[6] + wgb[0], l1 = s[7] + wgb[1], l2 = s[8] + wgb[2];
        float lm = fmaxf(l0, fmaxf(l1, l2));
        float g0 = expf(l0 - lm), g1 = expf(l1 - lm), g2 = expf(l2 - lm);
        float gs = g0 + g1 + g2;
        sc[0] = inv0; sc[1] = inv1; sc[2] = inv2;
        sc[3] = ex0 / es; sc[4] = ex1 / es; sc[5] = ex2 / es;
        sc[6] = g0 / gs; sc[7] = g1 / gs; sc[8] = g2 / gs;
        sc[9] = (k0 || k1 || k2) ? 1.f : 0.f;
    }
    __syncthreads();

    const float inv0 = sc[0], inv1 = sc[1], inv2 = sc[2];
    const float w0 = sc[3], w1 = sc[4], w2 = sc[5];
    const float f0 = sc[6], f1 = sc[7], f2 = sc[8];
    const bool any = sc[9] > 0.5f;

    float4 cm, ct;
    {
        const float a0[4] = {e0.x, e0.y, e0.z, e0.w};
        const float a1[4] = {e1.x, e1.y, e1.z, e1.w};
        const float a2[4] = {e2.x, e2.y, e2.z, e2.w};
        float cmv[4], ctv[4];
#pragma unroll
        for (int i = 0; i < 4; i++) {
            float v0 = a0[i], v1 = a1[i], v2 = a2[i];
            float n0 = v0 * inv0, n1 = v1 * inv1, n2 = v2 * inv2;
            float wsum = 0.f;
            if (n0 * n1 > THRV) wsum += w0 * 0.5f * (v0 + v1);
            if (n0 * n2 > THRV) wsum += w1 * 0.5f * (v0 + v2);
            if (n1 * n2 > THRV) wsum += w2 * 0.5f * (v1 + v2);
            float mean = (v0 + v1 + v2) * (1.f / 3.f);
            cmv[i] = rna_tf32(any ? wsum : mean);
            ctv[i] = rna_tf32(f0 * v0 + f1 * v1 + f2 * v2);
        }
        cm = make_float4(cmv[0], cmv[1], cmv[2], cmv[3]);
        ct = make_float4(ctv[0], ctv[1], ctv[2], ctv[3]);
    }
    *reinterpret_cast<float4*>(common + (size_t)b * 1024 + tid * 4) = cm;
    *reinterpret_cast<float4*>(cat + (size_t)b * 2048 + tid * 4) = ct;
}

// ---------------------------------------------------------------------------
extern "C" void kernel_launch(void* const* d_in, const int* in_sizes, int n_in,
                              void* d_out, int out_size)
{
    const float* xin[3] = {(const float*)d_in[0], (const float*)d_in[1], (const float*)d_in[2]};
    const float* w1[3]  = {(const float*)d_in[3], (const float*)d_in[7], (const float*)d_in[11]};
    const float* b1[3]  = {(const float*)d_in[4], (const float*)d_in[8], (const float*)d_in[12]};
    const float* w2[3]  = {(const float*)d_in[5], (const float*)d_in[9], (const float*)d_in[13]};
    const float* b2[3]  = {(const float*)d_in[6], (const float*)d_in[10], (const float*)d_in[14]};
    const float* wgW = (const float*)d_in[15]; const float* wgb = (const float*)d_in[16];
    const float* enhW = (const float*)d_in[17]; const float* enhb = (const float*)d_in[18];
    const float* fusW = (const float*)d_in[19]; const float* fusb = (const float*)d_in[20];
    float* out = (float*)d_out;

    float *H, *E, *C, *CAT, *WT1, *WT2, *ENT, *FUT;
    cudaGetSymbolAddress((void**)&H, g_H);
    cudaGetSymbolAddress((void**)&E, g_E);
    cudaGetSymbolAddress((void**)&C, g_C);
    cudaGetSymbolAddress((void**)&CAT, g_CAT);
    cudaGetSymbolAddress((void**)&WT1, g_WT1);
    cudaGetSymbolAddress((void**)&WT2, g_WT2);
    cudaGetSymbolAddress((void**)&ENT, g_enhT);
    cudaGetSymbolAddress((void**)&FUT, g_fusT);

    static cudaStream_t s2 = nullptr;
    static cudaEvent_t ev1 = nullptr, ev2 = nullptr, ev3 = nullptr, ev4 = nullptr;
    static bool init_done = false;
    if (!init_done) {
        cudaFuncSetAttribute((const void*)tgemm<2, 1, true, true>,  cudaFuncAttributeMaxDynamicSharedMemorySize, GSMEM128);
        cudaFuncSetAttribute((const void*)tgemm64<1, true, true>,   cudaFuncAttributeMaxDynamicSharedMemorySize, GSMEM128);
        cudaFuncSetAttribute((const void*)tgemm64<0, false, false>, cudaFuncAttributeMaxDynamicSharedMemorySize, GSMEM128);
        cudaFuncSetAttribute((const void*)tgemm64<2, false, true>,  cudaFuncAttributeMaxDynamicSharedMemorySize, GSMEM128);
        cudaStreamCreateWithFlags(&s2, cudaStreamNonBlocking);
        cudaEventCreateWithFlags(&ev1, cudaEventDisableTiming);
        cudaEventCreateWithFlags(&ev2, cudaEventDisableTiming);
        cudaEventCreateWithFlags(&ev3, cudaEventDisableTiming);
        cudaEventCreateWithFlags(&ev4, cudaEventDisableTiming);
        init_done = true;
    }

    dim3 tb(32, 8);
    const int Mt = 16384 / 128;   // 128 M-tiles
    const int Mh = Mt / 2;        // 64 tiles per half
    const long HSTR = 16384L * 304;

    // weight transposes (tf32-rounded) on the main stream (WT1 gates layer-1)
    P3 w1p = {w1[0], w1[1], w1[2]};
    P3 w2p = {w2[0], w2[1], w2[2]};
    transposeW<<<dim3(32, 12, 3), tb>>>(w1p, WT1, 384L * 1024, 1024, 300, 1024, 384);
    transposeW<<<dim3(10, 32, 3), tb>>>(w2p, WT2, 1024L * 304, 300, 1024, 304, 1024);

    // fork side stream: L1 tail + enh/fus transposes overlap L1 main
    cudaEventRecord(ev1, 0);
    cudaStreamWaitEvent(s2, ev1, 0);

    P3 aL1 = {xin[0], xin[1], xin[2]};
    P3 bL1 = {b1[0], b1[1], b1[2]};
    tgemm<2, 1, true, true><<<dim3(1, Mt, 3), 256, GSMEM128, s2>>>(
        aL1, 1024, WT1, 384L * 1024, 1024, bL1,
        H, HSTR, 304, 300, 304, 1024, 256, nullptr, 0);
    P3 enhp = {enhW, enhW, enhW};
    P3 fusp = {fusW, fusW, fusW};
    transposeW<<<dim3(32, 32, 1), tb, 0, s2>>>(enhp, ENT, 0, 1024, 1024, 1024, 1024);
    transposeW<<<dim3(64, 32, 1), tb, 0, s2>>>(fusp, FUT, 0, 2048, 1024, 2048, 1024);
    cudaEventRecord(ev2, s2);

    // main stream: L1 main (cols 0-255), full M
    tgemm64<1, true, true><<<dim3(2, Mt, 3), 128, GSMEM128>>>(
        aL1, 1024, WT1, 384L * 1024, 1024, bL1,
        H, HSTR, 304, 1024, 0, nullptr, 0);

    // join: H + ENT/FUT complete; then fork the two half-batch chains
    cudaStreamWaitEvent(0, ev2, 0);
    cudaEventRecord(ev3, 0);
    cudaStreamWaitEvent(s2, ev3, 0);

    P3 aL2 = {H, H + HSTR, H + 2 * HSTR};
    P3 bL2 = {b2[0], b2[1], b2[2]};
    P3 aEN = {C, C, C};
    P3 bEN = {enhb, enhb, enhb};
    P3 aFU = {CAT, CAT, CAT};
    P3 bFU = {fusb, fusb, fusb};

    // ---- half 0 on main stream ----
    tgemm64<0, false, false><<<dim3(8, Mh, 3), 128, GSMEM128>>>(
        aL2, 304, WT2, 1024L * 304, 304, bL2, E, 1024, 3072, 304, 0, nullptr, 0);
    rowfuse<<<8192, 256>>>(E, wgW, wgb, C, CAT, 0);
    tgemm64<2, false, true><<<dim3(8, Mh, 1), 128, GSMEM128>>>(
        aEN, 1024, ENT, 0, 1024, bEN, CAT + 1024, 0, 2048, 1024, 0, C, 1024);
    tgemm64<0, false, false><<<dim3(8, Mh, 1), 128, GSMEM128>>>(
        aFU, 2048, FUT, 0, 2048, bFU, out, 0, 1024, 2048, 0, nullptr, 0);

    // ---- half 1 on side stream (fully independent: row-wise chain) ----
    tgemm64<0, false, false><<<dim3(8, Mh, 3), 128, GSMEM128, s2>>>(
        aL2, 304, WT2, 1024L * 304, 304, bL2, E, 1024, 3072, 304, Mh, nullptr, 0);
    rowfuse<<<8192, 256, 0, s2>>>(E, wgW, wgb, C, CAT, 8192);
    tgemm64<2, false, true><<<dim3(8, Mh, 1), 128, GSMEM128, s2>>>(
        aEN, 1024, ENT, 0, 1024, bEN, CAT + 1024, 0, 2048, 1024, Mh, C, 1024);
    tgemm64<0, false, false><<<dim3(8, Mh, 1), 128, GSMEM128, s2>>>(
        aFU, 2048, FUT, 0, 2048, bFU, out, 0, 1024, 2048, Mh, nullptr, 0);

    // join side stream back into main before capture ends
    cudaEventRecord(ev4, s2);
    cudaStreamWaitEvent(0, ev4, 0);
}